// round 17
// baseline (speedup 1.0000x reference)
#include <cuda_runtime.h>
#include <stdint.h>
#include <math.h>

#define SEQ    2048
#define NQ     8
#define EMB    256
#define DIN    264     // EMB + HID
#define TAGS   50
#define CL     16      // chunk length (serial steps per pass)
#define NCHUNK (SEQ / CL)   // 128 chunks, one wave
#define TT     4       // tokens per proj block (512 blocks)

// Scratch (no allocation allowed).
__device__ float g_Xp[SEQ * 32];
__device__ float g_S1h[NCHUNK * NQ], g_S1c[NCHUNK * NQ];

__device__ __forceinline__ float tanh_approx(float x) {
    float r;
    asm("tanh.approx.f32 %0, %1;" : "=f"(r) : "f"(x));
    return r;
}
__device__ __forceinline__ void sts_f32(unsigned int a, float v) {
    asm volatile("st.volatile.shared.f32 [%0], %1;" :: "r"(a), "f"(v));
}
__device__ __forceinline__ float4 lds_v4(unsigned int a) {
    float4 r;
    asm volatile("ld.volatile.shared.v4.f32 {%0,%1,%2,%3}, [%4];"
                 : "=f"(r.x), "=f"(r.y), "=f"(r.z), "=f"(r.w) : "r"(a));
    return r;
}

// ---------------------------------------------------------------------------
// Kernel A: Xp[t][g*8+w] = emb[sent[t]] . W_g[w][:256] + b_g[w] + th_g[w]
// 4 tokens per block, 512 blocks. NO shuffles: the 8-partial reduction goes
// through volatile smem (same-warp in-order STS->LDS, warp convergent).
// ---------------------------------------------------------------------------
__global__ void __launch_bounds__(256)
proj_kernel(const int* __restrict__ sent,
            const float* __restrict__ emb,
            const float* __restrict__ Wf, const float* __restrict__ bf, const float* __restrict__ thf,
            const float* __restrict__ Wi, const float* __restrict__ bi, const float* __restrict__ thi,
            const float* __restrict__ Wu, const float* __restrict__ bu, const float* __restrict__ thu,
            const float* __restrict__ Wo, const float* __restrict__ bo, const float* __restrict__ tho)
{
    __shared__ int   ssent[TT];
    __shared__ __align__(16) float semb[TT][EMB];
    __shared__ __align__(16) float s_red[TT][256];   // per-tok partials [out*8+sub]

    const int tid = threadIdx.x;
    const int out = tid >> 3;   // 0..31 (g*8+w)
    const int sub = tid & 7;
    const int g   = out >> 3;
    const int w   = out & 7;
    const int base = blockIdx.x * TT;

    if (tid < TT) ssent[tid] = sent[base + tid];

    const float* W  = (g == 0) ? Wf  : (g == 1) ? Wi  : (g == 2) ? Wu  : Wo;
    const float* b  = (g == 0) ? bf  : (g == 1) ? bi  : (g == 2) ? bu  : bo;
    const float* th = (g == 0) ? thf : (g == 1) ? thi : (g == 2) ? thu : tho;

    // weight slice: 8 float4 covering cols sub*4 + 32*jj + {0..3}
    float4 w4[8];
    #pragma unroll
    for (int jj = 0; jj < 8; jj++)
        w4[jj] = *reinterpret_cast<const float4*>(W + w * DIN + sub * 4 + 32 * jj);
    const float bth = __ldg(&b[w]) + __ldg(&th[w]);

    const unsigned int A_red = (unsigned int)__cvta_generic_to_shared(&s_red[0][0]);

    __syncthreads();   // ssent ready
    // stage 4 emb rows: TT*EMB/4 == 256 float4 -> exactly one per thread
    {
        const int tok = tid >> 6;
        const int c4  = tid & 63;
        reinterpret_cast<float4*>(semb[tok])[c4] =
            reinterpret_cast<const float4*>(emb + (size_t)ssent[tok] * EMB)[c4];
    }
    __syncthreads();

    // partial dots -> volatile smem (no shfl)
    #pragma unroll
    for (int tok = 0; tok < TT; tok++) {
        float s = 0.f;
        #pragma unroll
        for (int jj = 0; jj < 8; jj++) {
            const float4 a = reinterpret_cast<const float4*>(semb[tok])[sub + 8 * jj];
            s = fmaf(a.x, w4[jj].x, s);
            s = fmaf(a.y, w4[jj].y, s);
            s = fmaf(a.z, w4[jj].z, s);
            s = fmaf(a.w, w4[jj].w, s);
        }
        sts_f32(A_red + 4u * (tok * 256 + out * 8 + sub), s);
    }

    // owner (sub==0) sums its 8 partials per tok: same-warp in-order smem
    if (sub == 0) {
        #pragma unroll
        for (int tok = 0; tok < TT; tok++) {
            const float4 p0 = lds_v4(A_red + 4u * (tok * 256 + out * 8));
            const float4 p1 = lds_v4(A_red + 4u * (tok * 256 + out * 8) + 16u);
            float s = ((p0.x + p0.y) + (p0.z + p0.w))
                    + ((p1.x + p1.y) + (p1.z + p1.w));
            g_Xp[(base + tok) * 32 + out] = s + bth;
        }
    }
}

// ---------------------------------------------------------------------------
// Shared step machinery (validated): lane = g*8+w; quantum layer == prefix
// products of cos(phi); cross-lane traffic via volatile smem (warp fully
// convergent -> no WARPSYNC). The kernel boundary IS the inter-pass sync.
// ---------------------------------------------------------------------------

// Pass 1: chunk k runs CL steps from (h,c)=0; records end state only.
__global__ void __launch_bounds__(32, 1)
pass1_kernel(const float* __restrict__ Wf, const float* __restrict__ Wi,
             const float* __restrict__ Wu, const float* __restrict__ Wo)
{
    __shared__ __align__(16) float s_cos[32];
    __shared__ __align__(16) float s_aT[32];
    __shared__ __align__(16) float s_h[8];

    const int lane = threadIdx.x;
    const int g = lane >> 3;
    const int w = lane & 7;
    const int k = blockIdx.x;

    float xp[CL];
    #pragma unroll
    for (int t = 0; t < CL; t++)
        xp[t] = __ldg(&g_Xp[(k * CL + t) * 32 + lane]);

    const unsigned int A_cos    = (unsigned int)__cvta_generic_to_shared(&s_cos[0]);
    const unsigned int A_aT     = (unsigned int)__cvta_generic_to_shared(&s_aT[0]);
    const unsigned int A_h      = (unsigned int)__cvta_generic_to_shared(&s_h[0]);
    const unsigned int A_cos_st = A_cos + 4u * lane;
    const unsigned int A_cos_l0 = A_cos + 32u * g;
    const unsigned int A_cos_l1 = A_cos + 32u * g + 16u;
    const unsigned int A_aT_st  = A_aT + 4u * (w * 4 + g);
    const unsigned int A_aT_ld  = A_aT + 16u * w;
    const unsigned int A_h_st   = A_h + 4u * w;
    const unsigned int A_h_l0   = A_h;
    const unsigned int A_h_l1   = A_h + 16u;

    const float* W = (g == 0) ? Wf : (g == 1) ? Wi : (g == 2) ? Wu : Wo;
    float wh[NQ];
    #pragma unroll
    for (int kk = 0; kk < NQ; kk++)
        wh[kk] = __ldg(W + w * DIN + EMB + kk);

    bool use[NQ];
    use[0] = (w != 0);
    #pragma unroll
    for (int kk = 1; kk < NQ; kk++)
        use[kk] = (w == 0) || (kk <= w);

    const float s0 = (g == 2) ? 1.0f : 0.5f;
    const float s1 = (g == 2) ? 1.0f : 0.5f;
    const float s2 = (g == 2) ? 0.0f : 0.5f;

    float h8[NQ];
    #pragma unroll
    for (int kk = 0; kk < NQ; kk++) h8[kk] = 0.f;
    float creg = 0.f;

    #pragma unroll
    for (int t = 0; t < CL; t++) {
        float y0 = xp[t], y1 = 0.f;
        y0 = fmaf(h8[0], wh[0], y0);
        y1 = fmaf(h8[1], wh[1], y1);
        y0 = fmaf(h8[2], wh[2], y0);
        y1 = fmaf(h8[3], wh[3], y1);
        y0 = fmaf(h8[4], wh[4], y0);
        y1 = fmaf(h8[5], wh[5], y1);
        y0 = fmaf(h8[6], wh[6], y0);
        y1 = fmaf(h8[7], wh[7], y1);
        float cw = __cosf(y0 + y1);

        sts_f32(A_cos_st, cw);
        const float4 cA = lds_v4(A_cos_l0);
        const float4 cB = lds_v4(A_cos_l1);

        float m0 = use[0] ? cA.x : 1.0f;
        float m1 = use[1] ? cA.y : 1.0f;
        float m2 = use[2] ? cA.z : 1.0f;
        float m3 = use[3] ? cA.w : 1.0f;
        float m4 = use[4] ? cB.x : 1.0f;
        float m5 = use[5] ? cB.y : 1.0f;
        float m6 = use[6] ? cB.z : 1.0f;
        float m7 = use[7] ? cB.w : 1.0f;
        float ev = ((m0 * m1) * (m2 * m3)) * ((m4 * m5) * (m6 * m7));

        float a = fmaf(s1, tanh_approx(s0 * ev), s2);

        sts_f32(A_aT_st, a);
        const float4 q = lds_v4(A_aT_ld);   // (f, i, u, o) of wire w

        float cn = fmaf(q.x, creg, q.y * q.z);
        creg = cn;
        float hw = q.w * tanh_approx(cn);

        sts_f32(A_h_st, hw);
        const float4 hA = lds_v4(A_h_l0);
        const float4 hB = lds_v4(A_h_l1);
        h8[0] = hA.x; h8[1] = hA.y; h8[2] = hA.z; h8[3] = hA.w;
        h8[4] = hB.x; h8[5] = hB.y; h8[6] = hB.z; h8[7] = hB.w;
    }

    if (lane < NQ) {
        g_S1h[k * NQ + w] = h8[w];
        g_S1c[k * NQ + w] = creg;
    }
}

// Pass 2: chunk k restarts from S1[k-1] (k=0 from zeros), runs CL steps,
// then computes the log-softmax head for its CL tokens inline (lanes 0..CL-1).
__global__ void __launch_bounds__(32, 1)
pass2_kernel(const float* __restrict__ Wf, const float* __restrict__ Wi,
             const float* __restrict__ Wu, const float* __restrict__ Wo,
             const float* __restrict__ Wt, const float* __restrict__ bt,
             float* __restrict__ outp)
{
    __shared__ __align__(16) float s_hist[CL * 8];
    __shared__ __align__(16) float s_wt[TAGS * 8];
    __shared__ __align__(16) float s_bt[TAGS];
    __shared__ __align__(16) float s_logit[TAGS * CL];
    __shared__ __align__(16) float s_cos[32];
    __shared__ __align__(16) float s_aT[32];
    __shared__ __align__(16) float s_h[8];

    const int lane = threadIdx.x;
    const int g = lane >> 3;
    const int w = lane & 7;
    const int k = blockIdx.x;

    float xp[CL];
    #pragma unroll
    for (int t = 0; t < CL; t++)
        xp[t] = __ldg(&g_Xp[(k * CL + t) * 32 + lane]);

    for (int i = lane; i < TAGS * 8; i += 32) s_wt[i] = __ldg(&Wt[i]);
    for (int i = lane; i < TAGS; i += 32)     s_bt[i] = __ldg(&bt[i]);

    const unsigned int A_cos    = (unsigned int)__cvta_generic_to_shared(&s_cos[0]);
    const unsigned int A_aT     = (unsigned int)__cvta_generic_to_shared(&s_aT[0]);
    const unsigned int A_h      = (unsigned int)__cvta_generic_to_shared(&s_h[0]);
    const unsigned int A_cos_st = A_cos + 4u * lane;
    const unsigned int A_cos_l0 = A_cos + 32u * g;
    const unsigned int A_cos_l1 = A_cos + 32u * g + 16u;
    const unsigned int A_aT_st  = A_aT + 4u * (w * 4 + g);
    const unsigned int A_aT_ld  = A_aT + 16u * w;
    const unsigned int A_h_st   = A_h + 4u * w;
    const unsigned int A_h_l0   = A_h;
    const unsigned int A_h_l1   = A_h + 16u;

    const float* W = (g == 0) ? Wf : (g == 1) ? Wi : (g == 2) ? Wu : Wo;
    float wh[NQ];
    #pragma unroll
    for (int kk = 0; kk < NQ; kk++)
        wh[kk] = __ldg(W + w * DIN + EMB + kk);

    bool use[NQ];
    use[0] = (w != 0);
    #pragma unroll
    for (int kk = 1; kk < NQ; kk++)
        use[kk] = (w == 0) || (kk <= w);

    const float s0 = (g == 2) ? 1.0f : 0.5f;
    const float s1 = (g == 2) ? 1.0f : 0.5f;
    const float s2 = (g == 2) ? 0.0f : 0.5f;

    float h8[NQ];
    float creg;
    if (k == 0) {
        #pragma unroll
        for (int kk = 0; kk < NQ; kk++) h8[kk] = 0.f;
        creg = 0.f;
    } else {
        #pragma unroll
        for (int kk = 0; kk < NQ; kk++)
            h8[kk] = __ldg(&g_S1h[(k - 1) * NQ + kk]);
        creg = __ldg(&g_S1c[(k - 1) * NQ + w]);
    }

    #pragma unroll
    for (int t = 0; t < CL; t++) {
        float y0 = xp[t], y1 = 0.f;
        y0 = fmaf(h8[0], wh[0], y0);
        y1 = fmaf(h8[1], wh[1], y1);
        y0 = fmaf(h8[2], wh[2], y0);
        y1 = fmaf(h8[3], wh[3], y1);
        y0 = fmaf(h8[4], wh[4], y0);
        y1 = fmaf(h8[5], wh[5], y1);
        y0 = fmaf(h8[6], wh[6], y0);
        y1 = fmaf(h8[7], wh[7], y1);
        float cw = __cosf(y0 + y1);

        sts_f32(A_cos_st, cw);
        const float4 cA = lds_v4(A_cos_l0);
        const float4 cB = lds_v4(A_cos_l1);

        float m0 = use[0] ? cA.x : 1.0f;
        float m1 = use[1] ? cA.y : 1.0f;
        float m2 = use[2] ? cA.z : 1.0f;
        float m3 = use[3] ? cA.w : 1.0f;
        float m4 = use[4] ? cB.x : 1.0f;
        float m5 = use[5] ? cB.y : 1.0f;
        float m6 = use[6] ? cB.z : 1.0f;
        float m7 = use[7] ? cB.w : 1.0f;
        float ev = ((m0 * m1) * (m2 * m3)) * ((m4 * m5) * (m6 * m7));

        float a = fmaf(s1, tanh_approx(s0 * ev), s2);

        sts_f32(A_aT_st, a);
        const float4 q = lds_v4(A_aT_ld);

        float cn = fmaf(q.x, creg, q.y * q.z);
        creg = cn;
        float hw = q.w * tanh_approx(cn);

        sts_f32(A_h_st, hw);
        if (lane < NQ)
            s_hist[t * 8 + w] = hw;
        const float4 hA = lds_v4(A_h_l0);
        const float4 hB = lds_v4(A_h_l1);
        h8[0] = hA.x; h8[1] = hA.y; h8[2] = hA.z; h8[3] = hA.w;
        h8[4] = hB.x; h8[5] = hB.y; h8[6] = hB.z; h8[7] = hB.w;
    }

    // ------------- head: token = k*CL + lane, lanes 0..CL-1 -------------
    __syncwarp();

    if (lane < CL) {
        float h[NQ];
        #pragma unroll
        for (int j = 0; j < NQ; j++)
            h[j] = s_hist[lane * 8 + j];

        float mx = -1e30f;
        #pragma unroll 1
        for (int tag = 0; tag < TAGS; tag++) {
            const float4 w0 = *reinterpret_cast<const float4*>(&s_wt[tag * 8]);
            const float4 w1 = *reinterpret_cast<const float4*>(&s_wt[tag * 8 + 4]);
            float s = s_bt[tag];
            s = fmaf(h[0], w0.x, s);
            s = fmaf(h[1], w0.y, s);
            s = fmaf(h[2], w0.z, s);
            s = fmaf(h[3], w0.w, s);
            s = fmaf(h[4], w1.x, s);
            s = fmaf(h[5], w1.y, s);
            s = fmaf(h[6], w1.z, s);
            s = fmaf(h[7], w1.w, s);
            s_logit[tag * CL + lane] = s;
            mx = fmaxf(mx, s);
        }

        float se = 0.f;
        #pragma unroll 1
        for (int tag = 0; tag < TAGS; tag++)
            se += __expf(s_logit[tag * CL + lane] - mx);
        const float lse = mx + logf(se);

        const int token = k * CL + lane;
        #pragma unroll 1
        for (int tag = 0; tag < TAGS; tag++)
            outp[token * TAGS + tag] = s_logit[tag * CL + lane] - lse;
    }
}

// ---------------------------------------------------------------------------
extern "C" void kernel_launch(void* const* d_in, const int* in_sizes, int n_in,
                              void* d_out, int out_size)
{
    const int*   sent = (const int*)  d_in[0];
    const float* emb  = (const float*)d_in[1];
    const float* Wf   = (const float*)d_in[2];
    const float* bf   = (const float*)d_in[3];
    const float* Wi   = (const float*)d_in[4];
    const float* bi   = (const float*)d_in[5];
    const float* Wu   = (const float*)d_in[6];
    const float* bu   = (const float*)d_in[7];
    const float* Wo   = (const float*)d_in[8];
    const float* bo   = (const float*)d_in[9];
    const float* thf  = (const float*)d_in[10];
    const float* thi  = (const float*)d_in[11];
    const float* thu  = (const float*)d_in[12];
    const float* tho  = (const float*)d_in[13];
    const float* Wt   = (const float*)d_in[14];
    const float* bt   = (const float*)d_in[15];
    float* out = (float*)d_out;

    proj_kernel<<<SEQ / TT, 256>>>(sent, emb,
                                   Wf, bf, thf,
                                   Wi, bi, thi,
                                   Wu, bu, thu,
                                   Wo, bo, tho);
    pass1_kernel<<<NCHUNK, 32>>>(Wf, Wi, Wu, Wo);
    pass2_kernel<<<NCHUNK, 32>>>(Wf, Wi, Wu, Wo, Wt, bt, out);
}